// round 1
// baseline (speedup 1.0000x reference)
#include <cuda_runtime.h>
#include <cuda_bf16.h>

// Problem dims (fixed by the reference)
#define FDIM 1024   // in_partitions * in_nodes
#define CDIM 128    // out_classes
#define BDIM 2048   // batch

// Scratch: transposed softmax(weight): WexpT[f][c] = softmax(weight[c,:])[f]
__device__ float g_wexpT[FDIM * CDIM];

// ---------------------------------------------------------------------------
// Kernel 1: row softmax of weight (C rows of F), write transposed.
// exp(log_softmax(w))[c,f] = exp(w[c,f]-max_c) / sum_f exp(w[c,f]-max_c)
// ---------------------------------------------------------------------------
__global__ void __launch_bounds__(256) softmax_w_kernel(const float* __restrict__ w) {
    const int c = blockIdx.x;
    const float* row = w + c * FDIM;
    __shared__ float red[256];
    const int t = threadIdx.x;

    float m = -1e30f;
    for (int f = t; f < FDIM; f += 256) m = fmaxf(m, row[f]);
    red[t] = m;
    __syncthreads();
    for (int s = 128; s > 0; s >>= 1) {
        if (t < s) red[t] = fmaxf(red[t], red[t + s]);
        __syncthreads();
    }
    m = red[0];
    __syncthreads();

    float sum = 0.0f;
    for (int f = t; f < FDIM; f += 256) sum += __expf(row[f] - m);
    red[t] = sum;
    __syncthreads();
    for (int s = 128; s > 0; s >>= 1) {
        if (t < s) red[t] += red[t + s];
        __syncthreads();
    }
    const float inv = 1.0f / red[0];

    for (int f = t; f < FDIM; f += 256)
        g_wexpT[f * CDIM + c] = __expf(row[f] - m) * inv;
}

// ---------------------------------------------------------------------------
// Kernel 2: out[b,c] = log( sum_f exp(x[b,f]) * WexpT[f,c] )
// Tiled SGEMM: BM=16, BN=128 (all classes), BK=64. 128 threads.
// warp w handles output rows [w*4, w*4+4); lane l handles cols [l*4, l*4+4).
// exp() fused into the A-tile load; log() fused into the epilogue.
// ---------------------------------------------------------------------------
#define BM 16
#define BN 128
#define BK 64

__global__ void __launch_bounds__(128) lse_gemm_kernel(const float* __restrict__ x,
                                                       float* __restrict__ out) {
    __shared__ float As[BM][BK + 4];   // +4 pad: de-conflict STS
    __shared__ float Bs[BK][BN];

    const int b0   = blockIdx.x * BM;
    const int tid  = threadIdx.x;
    const int warp = tid >> 5;
    const int lane = tid & 31;

    // A-load mapping: 16 rows x 16 float4s per row; 2 float4 per thread
    const int arow = tid >> 3;   // 0..15
    const int af4  = tid & 7;    // 0..7 (x2 via j)
    // B-load mapping: 64 rows x 32 float4s; 16 float4 per thread
    const int bk0  = tid >> 5;   // 0..3 (step 4 via j)
    const int bc4  = tid & 31;   // float4 column index

    float acc[4][4];
#pragma unroll
    for (int i = 0; i < 4; i++)
#pragma unroll
        for (int j = 0; j < 4; j++) acc[i][j] = 0.0f;

    for (int k0 = 0; k0 < FDIM; k0 += BK) {
        // --- load A tile, fuse exp ---
#pragma unroll
        for (int j = 0; j < 2; j++) {
            const int kf = af4 + j * 8;
            float4 v = *reinterpret_cast<const float4*>(
                &x[(size_t)(b0 + arow) * FDIM + k0 + kf * 4]);
            float4 e = make_float4(__expf(v.x), __expf(v.y), __expf(v.z), __expf(v.w));
            *reinterpret_cast<float4*>(&As[arow][kf * 4]) = e;
        }
        // --- load B tile (already transposed in scratch: contiguous rows) ---
#pragma unroll
        for (int j = 0; j < 16; j++) {
            const int kk = bk0 + j * 4;
            float4 v = *reinterpret_cast<const float4*>(
                &g_wexpT[(size_t)(k0 + kk) * CDIM + bc4 * 4]);
            *reinterpret_cast<float4*>(&Bs[kk][bc4 * 4]) = v;
        }
        __syncthreads();

        // --- compute ---
#pragma unroll 8
        for (int k = 0; k < BK; k++) {
            const float a0 = As[warp * 4 + 0][k];
            const float a1 = As[warp * 4 + 1][k];
            const float a2 = As[warp * 4 + 2][k];
            const float a3 = As[warp * 4 + 3][k];
            const float4 bv = *reinterpret_cast<float4*>(&Bs[k][lane * 4]);
            acc[0][0] += a0 * bv.x; acc[0][1] += a0 * bv.y;
            acc[0][2] += a0 * bv.z; acc[0][3] += a0 * bv.w;
            acc[1][0] += a1 * bv.x; acc[1][1] += a1 * bv.y;
            acc[1][2] += a1 * bv.z; acc[1][3] += a1 * bv.w;
            acc[2][0] += a2 * bv.x; acc[2][1] += a2 * bv.y;
            acc[2][2] += a2 * bv.z; acc[2][3] += a2 * bv.w;
            acc[3][0] += a3 * bv.x; acc[3][1] += a3 * bv.y;
            acc[3][2] += a3 * bv.z; acc[3][3] += a3 * bv.w;
        }
        __syncthreads();
    }

    // --- epilogue: log + store ---
#pragma unroll
    for (int r = 0; r < 4; r++) {
        const int b = b0 + warp * 4 + r;
        float4 o = make_float4(__logf(acc[r][0]), __logf(acc[r][1]),
                               __logf(acc[r][2]), __logf(acc[r][3]));
        *reinterpret_cast<float4*>(&out[(size_t)b * CDIM + lane * 4]) = o;
    }
}

// ---------------------------------------------------------------------------
extern "C" void kernel_launch(void* const* d_in, const int* in_sizes, int n_in,
                              void* d_out, int out_size) {
    // Identify inputs by size (robust to ordering): x = 2048*16*64, w = 128*1024
    const float* x = (const float*)d_in[0];
    const float* w = (const float*)d_in[1];
    if (n_in >= 2 && in_sizes[0] == CDIM * FDIM && in_sizes[1] == BDIM * FDIM) {
        w = (const float*)d_in[0];
        x = (const float*)d_in[1];
    }
    float* out = (float*)d_out;

    softmax_w_kernel<<<CDIM, 256>>>(w);
    lse_gemm_kernel<<<BDIM / BM, 128>>>(x, out);
}

// round 3
// speedup vs baseline: 2.2021x; 2.2021x over previous
#include <cuda_runtime.h>
#include <cuda_bf16.h>
#include <cstdint>

// Problem dims (fixed)
#define FDIM 1024
#define CDIM 128
#define BDIM 2048

#define KSPLIT 2
#define KCTA  (FDIM / KSPLIT)   // 512
#define BM 32
#define BN 128
#define BK 64
#define NITER (KCTA / BK)       // 8

// ---------------- scratch (static device, no allocs) ----------------
__device__ __nv_bfloat16 g_ah[BDIM * FDIM];   // exp(x) hi
__device__ __nv_bfloat16 g_al[BDIM * FDIM];   // exp(x) lo
__device__ __nv_bfloat16 g_bh[CDIM * FDIM];   // softmax(w) hi
__device__ __nv_bfloat16 g_bl[CDIM * FDIM];   // softmax(w) lo
__device__ float g_part[KSPLIT * BDIM * CDIM];

// ---------------- helpers ----------------
__device__ __forceinline__ uint32_t smem_u32(const void* p) {
    uint32_t a;
    asm("{ .reg .u64 t; cvta.to.shared.u64 t, %1; cvt.u32.u64 %0, t; }" : "=r"(a) : "l"(p));
    return a;
}
// 128B-row swizzle: byte col ^ ((row&7)<<4), 16B granularity
__device__ __forceinline__ uint32_t swz(uint32_t row, uint32_t colByte) {
    return row * 128u + (colByte ^ ((row & 7u) << 4));
}
#define CP_ASYNC16(sm, g) asm volatile("cp.async.cg.shared.global [%0], [%1], 16;" :: "r"(sm), "l"(g) : "memory")
#define CP_COMMIT()       asm volatile("cp.async.commit_group;" ::: "memory")
#define CP_WAIT1()        asm volatile("cp.async.wait_group 1;" ::: "memory")
#define CP_WAIT0()        asm volatile("cp.async.wait_group 0;" ::: "memory")

#define LDMATRIX_X4(r0, r1, r2, r3, addr)                                     \
    asm volatile("ldmatrix.sync.aligned.m8n8.x4.shared.b16 {%0,%1,%2,%3}, [%4];" \
                 : "=r"(r0), "=r"(r1), "=r"(r2), "=r"(r3) : "r"(addr))

#define MMA_BF16(d, a, b)                                                     \
    asm volatile("mma.sync.aligned.m16n8k16.row.col.f32.bf16.bf16.f32 "       \
                 "{%0,%1,%2,%3}, {%4,%5,%6,%7}, {%8,%9}, {%0,%1,%2,%3};"      \
                 : "+f"((d)[0]), "+f"((d)[1]), "+f"((d)[2]), "+f"((d)[3])     \
                 : "r"((a)[0]), "r"((a)[1]), "r"((a)[2]), "r"((a)[3]),        \
                   "r"((b)[0]), "r"((b)[1]))

__device__ __forceinline__ void split_bf16(float v, __nv_bfloat16& h, __nv_bfloat16& l) {
    h = __float2bfloat16(v);
    l = __float2bfloat16(v - __bfloat162float(h));
}

// ---------------------------------------------------------------------------
// Kernel 1: softmax(weight) rows -> Bh/Bl  [C, F] K-major
// ---------------------------------------------------------------------------
__global__ void __launch_bounds__(256) prep_w_kernel(const float* __restrict__ w) {
    const int c = blockIdx.x;
    const float* row = w + c * FDIM;
    __shared__ float red[256];
    const int t = threadIdx.x;

    float m = -1e30f;
    for (int f = t; f < FDIM; f += 256) m = fmaxf(m, row[f]);
    red[t] = m;
    __syncthreads();
    for (int s = 128; s > 0; s >>= 1) { if (t < s) red[t] = fmaxf(red[t], red[t + s]); __syncthreads(); }
    m = red[0];
    __syncthreads();

    float sum = 0.0f;
    for (int f = t; f < FDIM; f += 256) sum += __expf(row[f] - m);
    red[t] = sum;
    __syncthreads();
    for (int s = 128; s > 0; s >>= 1) { if (t < s) red[t] += red[t + s]; __syncthreads(); }
    const float inv = 1.0f / red[0];

    for (int f = t; f < FDIM; f += 256) {
        float p = __expf(row[f] - m) * inv;
        __nv_bfloat16 h, l;
        split_bf16(p, h, l);
        g_bh[c * FDIM + f] = h;
        g_bl[c * FDIM + f] = l;
    }
}

// ---------------------------------------------------------------------------
// Kernel 2: exp(x) -> Ah/Al
// ---------------------------------------------------------------------------
__global__ void __launch_bounds__(256) prep_x_kernel(const float* __restrict__ x) {
    const size_t i4 = (size_t)blockIdx.x * 256 + threadIdx.x;
    float4 v = reinterpret_cast<const float4*>(x)[i4];
    float e0 = __expf(v.x), e1 = __expf(v.y), e2 = __expf(v.z), e3 = __expf(v.w);
    __nv_bfloat16 h0, l0, h1, l1, h2, l2, h3, l3;
    split_bf16(e0, h0, l0); split_bf16(e1, h1, l1);
    split_bf16(e2, h2, l2); split_bf16(e3, h3, l3);
    ushort4 hv = make_ushort4(__bfloat16_as_ushort(h0), __bfloat16_as_ushort(h1),
                              __bfloat16_as_ushort(h2), __bfloat16_as_ushort(h3));
    ushort4 lv = make_ushort4(__bfloat16_as_ushort(l0), __bfloat16_as_ushort(l1),
                              __bfloat16_as_ushort(l2), __bfloat16_as_ushort(l3));
    reinterpret_cast<ushort4*>(g_ah)[i4] = hv;
    reinterpret_cast<ushort4*>(g_al)[i4] = lv;
}

// ---------------------------------------------------------------------------
// Kernel 3: HMMA GEMM. grid = 64 Mtiles x 2 Ksplits = 128 CTAs, 128 threads.
// D[32,128] += Ah@Bh^T + Al@Bh^T + Ah@Bl^T over its K=512 slice.
// Double-buffered cp.async stages; SW128-swizzled tiles; ldmatrix.x4 frags.
// ---------------------------------------------------------------------------
// Per-stage smem layout (bytes):
#define OFF_AH 0
#define OFF_AL 4096
#define OFF_BH 8192
#define OFF_BL 24576
#define STAGE_BYTES 40960
#define SMEM_TOTAL (2 * STAGE_BYTES)   // 81920

__device__ __forceinline__ void issue_stage_loads(uint32_t stageBase, int mtile, int kOff, int tid) {
    // A tiles: 32 rows x 128B = 256 16B-chunks -> 2 per thread
#pragma unroll
    for (int t = 0; t < 2; t++) {
        const int idx = tid + t * 128;
        const uint32_t row = idx >> 3;       // 0..31
        const uint32_t c   = idx & 7;        // 16B chunk
        const __nv_bfloat16* ga = g_ah + (size_t)(mtile * BM + row) * FDIM + kOff + c * 8;
        const __nv_bfloat16* gl = g_al + (size_t)(mtile * BM + row) * FDIM + kOff + c * 8;
        CP_ASYNC16(stageBase + OFF_AH + swz(row, c * 16), ga);
        CP_ASYNC16(stageBase + OFF_AL + swz(row, c * 16), gl);
    }
    // B tiles: 128 rows x 128B = 1024 chunks -> 8 per thread
#pragma unroll
    for (int t = 0; t < 8; t++) {
        const int idx = tid + t * 128;
        const uint32_t row = idx >> 3;       // 0..127
        const uint32_t c   = idx & 7;
        const __nv_bfloat16* gb = g_bh + (size_t)row * FDIM + kOff + c * 8;
        const __nv_bfloat16* gc = g_bl + (size_t)row * FDIM + kOff + c * 8;
        CP_ASYNC16(stageBase + OFF_BH + swz(row, c * 16), gb);
        CP_ASYNC16(stageBase + OFF_BL + swz(row, c * 16), gc);
    }
    CP_COMMIT();
}

__global__ void __launch_bounds__(128) mma_kernel() {
    extern __shared__ char smem[];
    const uint32_t sbase = smem_u32(smem);
    const int tid  = threadIdx.x;
    const int warp = tid >> 5;     // n-range [warp*32, warp*32+32)
    const int lane = tid & 31;

    const int mtile = blockIdx.x >> 1;   // 0..63
    const int ks    = blockIdx.x & 1;    // 0..1
    const int k0    = ks * KCTA;

    float acc[2][4][4];                  // [mfrag][nfrag][4]
#pragma unroll
    for (int i = 0; i < 2; i++)
#pragma unroll
        for (int j = 0; j < 4; j++)
#pragma unroll
            for (int e = 0; e < 4; e++) acc[i][j][e] = 0.0f;

    // ldmatrix per-lane address components
    // A: row = mi*16 + (lane&7) + ((lane>>3)&1)*8 ; colByte = kstep*32 + (lane>>4)*16
    const uint32_t aRow = (lane & 7) + ((lane >> 3) & 1) * 8;
    const uint32_t aCol = (lane >> 4) * 16;
    // B: row(n) = nb + ((lane>>4)&1)*8 + (lane&7) ; colByte = kstep*32 + ((lane>>3)&1)*16
    const uint32_t bRow = ((lane >> 4) & 1) * 8 + (lane & 7);
    const uint32_t bCol = ((lane >> 3) & 1) * 16;

    issue_stage_loads(sbase, mtile, k0, tid);

    for (int it = 0; it < NITER; it++) {
        const uint32_t cur = sbase + (uint32_t)(it & 1) * STAGE_BYTES;
        if (it + 1 < NITER) {
            issue_stage_loads(sbase + (uint32_t)((it + 1) & 1) * STAGE_BYTES,
                              mtile, k0 + (it + 1) * BK, tid);
            CP_WAIT1();
        } else {
            CP_WAIT0();
        }
        __syncthreads();

#pragma unroll
        for (int kstep = 0; kstep < BK / 16; kstep++) {
            const uint32_t kb = kstep * 32;
            uint32_t ah[2][4], al[2][4];
#pragma unroll
            for (int mi = 0; mi < 2; mi++) {
                const uint32_t row = mi * 16 + aRow;
                LDMATRIX_X4(ah[mi][0], ah[mi][1], ah[mi][2], ah[mi][3],
                            cur + OFF_AH + swz(row, kb + aCol));
                LDMATRIX_X4(al[mi][0], al[mi][1], al[mi][2], al[mi][3],
                            cur + OFF_AL + swz(row, kb + aCol));
            }
            uint32_t bh[4][2], bl[4][2];
#pragma unroll
            for (int j = 0; j < 2; j++) {     // each x4 covers 2 n8-tiles
                const uint32_t row = warp * 32 + j * 16 + bRow;
                uint32_t r0, r1, r2, r3;
                LDMATRIX_X4(r0, r1, r2, r3, cur + OFF_BH + swz(row, kb + bCol));
                bh[j * 2 + 0][0] = r0; bh[j * 2 + 0][1] = r1;
                bh[j * 2 + 1][0] = r2; bh[j * 2 + 1][1] = r3;
                LDMATRIX_X4(r0, r1, r2, r3, cur + OFF_BL + swz(row, kb + bCol));
                bl[j * 2 + 0][0] = r0; bl[j * 2 + 0][1] = r1;
                bl[j * 2 + 1][0] = r2; bl[j * 2 + 1][1] = r3;
            }
#pragma unroll
            for (int ni = 0; ni < 4; ni++)
#pragma unroll
                for (int mi = 0; mi < 2; mi++) {
                    MMA_BF16(acc[mi][ni], ah[mi], bh[ni]);
                    MMA_BF16(acc[mi][ni], al[mi], bh[ni]);
                    MMA_BF16(acc[mi][ni], ah[mi], bl[ni]);
                }
        }
        __syncthreads();
    }

    // Epilogue: write fp32 partials
    float* part = g_part + (size_t)ks * (BDIM * CDIM);
#pragma unroll
    for (int mi = 0; mi < 2; mi++) {
#pragma unroll
        for (int ni = 0; ni < 4; ni++) {
            const int m = mtile * BM + mi * 16 + (lane >> 2);
            const int n = warp * 32 + ni * 8 + (lane & 3) * 2;
            *reinterpret_cast<float2*>(part + (size_t)m * CDIM + n) =
                make_float2(acc[mi][ni][0], acc[mi][ni][1]);
            *reinterpret_cast<float2*>(part + (size_t)(m + 8) * CDIM + n) =
                make_float2(acc[mi][ni][2], acc[mi][ni][3]);
        }
    }
}

// ---------------------------------------------------------------------------
// Kernel 4: reduce K-split partials + log
// ---------------------------------------------------------------------------
__global__ void __launch_bounds__(256) reduce_kernel(float* __restrict__ out) {
    const size_t idx = (size_t)blockIdx.x * 256 + threadIdx.x;
    float s = g_part[idx] + g_part[(size_t)(BDIM * CDIM) + idx];
    out[idx] = __logf(s);
}

// ---------------------------------------------------------------------------
extern "C" void kernel_launch(void* const* d_in, const int* in_sizes, int n_in,
                              void* d_out, int out_size) {
    const float* x = (const float*)d_in[0];
    const float* w = (const float*)d_in[1];
    if (n_in >= 2 && in_sizes[0] == CDIM * FDIM && in_sizes[1] == BDIM * FDIM) {
        w = (const float*)d_in[0];
        x = (const float*)d_in[1];
    }
    float* out = (float*)d_out;

    static bool attr_set = false;
    if (!attr_set) {
        cudaFuncSetAttribute(mma_kernel, cudaFuncAttributeMaxDynamicSharedMemorySize, SMEM_TOTAL);
        attr_set = true;
    }

    prep_w_kernel<<<CDIM, 256>>>(w);
    prep_x_kernel<<<(BDIM * FDIM) / (256 * 4), 256>>>(x);
    mma_kernel<<<(BDIM / BM) * KSPLIT, 128, SMEM_TOTAL>>>();
    reduce_kernel<<<(BDIM * CDIM) / 256, 256>>>(out);
}